// round 7
// baseline (speedup 1.0000x reference)
#include <cuda_runtime.h>

// Problem constants
#define NB 2
#define LB 1024
#define EB 256
#define HB 8
#define PB 4
#define KK 4
#define DB 32
#define MROWS (NB*LB)        // 2048
#define NH (NB*HB)           // 16
#define QPB (LB*PB)          // 4096 queries per batch-head
#define QTOT (NH*QPB)        // 65536
#define NTILE 64             // ref tiles per batch
#define TS 16                // refs per tile

// ---------------- scratch (device globals) ---------------------------------
__device__ float  g_val [MROWS*EB];
__device__ float  g_off [MROWS*96];
__device__ float  g_attn[MROWS*32];
__device__ float  g_attw[QTOT];
__device__ float4 g_sl  [QTOT];             // sampling loc (x,y,z,|s|^2)
__device__ int    g_qperm[QTOT];            // per-b permutation (Morton sorted)
__device__ float4 g_refPts[NB][LB];         // Morton-sorted refs (x,y,z,|r|^2)
__device__ int    g_refIdx[NB][LB];         // original ref index
__device__ float4 g_tileBnd[NB][NTILE];     // tile center (xyz) + radius (w)
__device__ int    g_idx [QTOT*KK];
__device__ float  g_w   [QTOT*KK];
__device__ float  g_A   [MROWS*EB];

// ---------------- packed f32x2 helpers (Blackwell) --------------------------
typedef unsigned long long u64;
__device__ __forceinline__ u64 pk(float lo, float hi) {
    u64 v; asm("mov.b64 %0, {%1, %2};" : "=l"(v) : "f"(lo), "f"(hi)); return v;
}
__device__ __forceinline__ void upk(u64 v, float& lo, float& hi) {
    asm("mov.b64 {%0, %1}, %2;" : "=f"(lo), "=f"(hi) : "l"(v));
}
__device__ __forceinline__ u64 fma2(u64 a, u64 b, u64 c) {
    u64 d; asm("fma.rn.f32x2 %0, %1, %2, %3;" : "=l"(d) : "l"(a), "l"(b), "l"(c)); return d;
}
__device__ __forceinline__ u64 mul2(u64 a, u64 b) {
    u64 d; asm("mul.rn.f32x2 %0, %1, %2;" : "=l"(d) : "l"(a), "l"(b)); return d;
}
__device__ __forceinline__ u64 add2(u64 a, u64 b) {
    u64 d; asm("add.rn.f32x2 %0, %1, %2;" : "=l"(d) : "l"(a), "l"(b)); return d;
}

// ---------------- generic 64x64 tiled SGEMM with bias ----------------------
__device__ __forceinline__ void sgemm256_body(const float* __restrict__ A,
                                              const float* __restrict__ B,
                                              const float* __restrict__ bias,
                                              float* __restrict__ C) {
    const int K = 256, NC = 256;
    __shared__ float As[16][64];
    __shared__ float Bs[16][68];
    const int tid = threadIdx.x;
    const int tx = tid & 15, ty = tid >> 4;
    const int rowBase = blockIdx.y * 64;
    const int colBase = blockIdx.x * 64;
    float acc[4][4];
    #pragma unroll
    for (int i = 0; i < 4; i++)
        #pragma unroll
        for (int j = 0; j < 4; j++) acc[i][j] = 0.f;

    for (int k0 = 0; k0 < K; k0 += 16) {
        #pragma unroll
        for (int i = 0; i < 4; i++) {
            int idx = tid + i*256;
            int m = idx >> 4, k = idx & 15;
            As[k][m] = A[(rowBase + m)*K + k0 + k];
        }
        #pragma unroll
        for (int i = 0; i < 4; i++) {
            int idx = tid + i*256;
            int k = idx >> 6, n = idx & 63;
            Bs[k][n] = B[(k0 + k)*NC + colBase + n];
        }
        __syncthreads();
        #pragma unroll
        for (int kk = 0; kk < 16; kk++) {
            float4 av = *(const float4*)&As[kk][ty*4];
            float4 bv = *(const float4*)&Bs[kk][tx*4];
            float a[4] = {av.x, av.y, av.z, av.w};
            float b[4] = {bv.x, bv.y, bv.z, bv.w};
            #pragma unroll
            for (int i = 0; i < 4; i++)
                #pragma unroll
                for (int j = 0; j < 4; j++)
                    acc[i][j] = fmaf(a[i], b[j], acc[i][j]);
        }
        __syncthreads();
    }
    #pragma unroll
    for (int i = 0; i < 4; i++) {
        int gm = rowBase + ty*4 + i;
        #pragma unroll
        for (int j = 0; j < 4; j++) {
            int gn = colBase + tx*4 + j;
            C[gm*NC + gn] = acc[i][j] + bias[gn];
        }
    }
}

__global__ void gemm_val_k(const float* A, const float* B, const float* bias) {
    sgemm256_body(A, B, bias, g_val);
}
__global__ void gemm_out_k(const float* B, const float* bias, float* C) {
    sgemm256_body(g_A, B, bias, C);
}

// Merged off(96) + attn(32) projection: 128 virtual columns
__global__ void gemm_oa_k(const float* __restrict__ A,
                          const float* __restrict__ W_off,  const float* __restrict__ b_off,
                          const float* __restrict__ W_attn, const float* __restrict__ b_attn) {
    const int K = 256;
    __shared__ float As[16][64];
    __shared__ float Bs[16][68];
    const int tid = threadIdx.x;
    const int tx = tid & 15, ty = tid >> 4;
    const int rowBase = blockIdx.y * 64;
    const int colBase = blockIdx.x * 64;   // 0 or 64
    float acc[4][4];
    #pragma unroll
    for (int i = 0; i < 4; i++)
        #pragma unroll
        for (int j = 0; j < 4; j++) acc[i][j] = 0.f;

    for (int k0 = 0; k0 < K; k0 += 16) {
        #pragma unroll
        for (int i = 0; i < 4; i++) {
            int idx = tid + i*256;
            int m = idx >> 4, k = idx & 15;
            As[k][m] = A[(rowBase + m)*K + k0 + k];
        }
        #pragma unroll
        for (int i = 0; i < 4; i++) {
            int idx = tid + i*256;
            int k = idx >> 6, n = idx & 63;
            int gn = colBase + n;
            int gk = k0 + k;
            Bs[k][n] = (gn < 96) ? W_off[gk*96 + gn] : W_attn[gk*32 + (gn - 96)];
        }
        __syncthreads();
        #pragma unroll
        for (int kk = 0; kk < 16; kk++) {
            float4 av = *(const float4*)&As[kk][ty*4];
            float4 bv = *(const float4*)&Bs[kk][tx*4];
            float a[4] = {av.x, av.y, av.z, av.w};
            float b[4] = {bv.x, bv.y, bv.z, bv.w};
            #pragma unroll
            for (int i = 0; i < 4; i++)
                #pragma unroll
                for (int j = 0; j < 4; j++)
                    acc[i][j] = fmaf(a[i], b[j], acc[i][j]);
        }
        __syncthreads();
    }
    #pragma unroll
    for (int i = 0; i < 4; i++) {
        int gm = rowBase + ty*4 + i;
        #pragma unroll
        for (int j = 0; j < 4; j++) {
            int gn = colBase + tx*4 + j;
            if (gn < 96) g_off[gm*96 + gn]         = acc[i][j] + b_off[gn];
            else         g_attn[gm*32 + (gn - 96)] = acc[i][j] + b_attn[gn - 96];
        }
    }
}

// ---------------- Morton helpers -------------------------------------------
__device__ __forceinline__ int spread3(int x) {
    return (x & 1) | ((x & 2) << 2) | ((x & 4) << 4);
}
__device__ __forceinline__ int cell8(float v) {
    int c = (int)floorf(v * 8.f);
    return min(max(c, 0), 7);
}
__device__ __forceinline__ int morton(float x, float y, float z) {
    return spread3(cell8(x)) | (spread3(cell8(y)) << 1) | (spread3(cell8(z)) << 2);
}

// ---------------- ref Morton sort + tile bounds (grid=2, block=256) --------
__global__ void refsort_k(const float* __restrict__ rp) {
    __shared__ float sx[LB], sy[LB], sz[LB];
    __shared__ int   sidx[LB], skey[LB];
    __shared__ int   cnt[512], bstart[512];
    __shared__ int   wsum[8];
    const int n = blockIdx.x, tid = threadIdx.x;
    const int lane = tid & 31, w = tid >> 5;
    const float* rpb = rp + n*LB*3;

    cnt[tid] = 0; cnt[tid + 256] = 0;
    __syncthreads();
    #pragma unroll
    for (int j = 0; j < 4; j++) {
        int i = tid + j*256;
        float x = rpb[3*i], y = rpb[3*i+1], z = rpb[3*i+2];
        int key = morton(x, y, z);
        skey[i] = key;
        atomicAdd(&cnt[key], 1);
    }
    __syncthreads();
    int c0 = cnt[2*tid], c1 = cnt[2*tid + 1];
    int s = c0 + c1, v = s;
    #pragma unroll
    for (int off = 1; off < 32; off <<= 1) {
        int u = __shfl_up_sync(0xffffffffu, v, off);
        if (lane >= off) v += u;
    }
    if (lane == 31) wsum[w] = v;
    __syncthreads();
    if (tid == 0) {
        int acc = 0;
        #pragma unroll
        for (int i = 0; i < 8; i++) { int t = wsum[i]; wsum[i] = acc; acc += t; }
    }
    __syncthreads();
    int excl = v - s + wsum[w];
    bstart[2*tid] = excl; bstart[2*tid + 1] = excl + c0;
    __syncthreads();
    #pragma unroll
    for (int j = 0; j < 4; j++) {
        int i = tid + j*256;
        int slot = atomicAdd(&bstart[skey[i]], 1);
        sx[slot] = rpb[3*i]; sy[slot] = rpb[3*i+1]; sz[slot] = rpb[3*i+2];
        sidx[slot] = i;
    }
    __syncthreads();
    #pragma unroll
    for (int j = 0; j < 4; j++) {
        int i = tid + j*256;
        float x = sx[i], y = sy[i], z = sz[i];
        g_refPts[n][i] = make_float4(x, y, z, x*x + y*y + z*z);
        g_refIdx[n][i] = sidx[i];
    }
    // tile AABB bounds: thread t handles tile t
    if (tid < NTILE) {
        float mnx = 3e38f, mny = 3e38f, mnz = 3e38f;
        float mxx = -3e38f, mxy = -3e38f, mxz = -3e38f;
        #pragma unroll
        for (int p = 0; p < TS; p++) {
            int i = tid*TS + p;
            mnx = fminf(mnx, sx[i]); mxx = fmaxf(mxx, sx[i]);
            mny = fminf(mny, sy[i]); mxy = fmaxf(mxy, sy[i]);
            mnz = fminf(mnz, sz[i]); mxz = fmaxf(mxz, sz[i]);
        }
        float cx = 0.5f*(mnx + mxx), cy = 0.5f*(mny + mxy), cz = 0.5f*(mnz + mxz);
        float ex = 0.5f*(mxx - mnx), ey = 0.5f*(mxy - mny), ez = 0.5f*(mxz - mnz);
        float rad = sqrtf(ex*ex + ey*ey + ez*ez) + 1e-3f;
        g_tileBnd[n][tid] = make_float4(cx, cy, cz, rad);
    }
}

// ---------------- fused prep + Morton counting sort (16 blocks, 512 thr) ---
__global__ void sortprep_k(const float* __restrict__ rp) {
    __shared__ int skey[QPB];
    __shared__ int cnt[512];
    __shared__ int bstart[512];
    __shared__ int wsum[16];
    const int b = blockIdx.x, tid = threadIdx.x;
    const int lane = tid & 31, w = tid >> 5;
    const int n = b >> 3, h = b & 7;

    cnt[tid] = 0;
    __syncthreads();

    #pragma unroll
    for (int j = 0; j < 8; j++) {
        int qi = tid + j*512;
        int l = qi >> 2, p = qi & 3;
        int m = n*LB + l;
        int q = b*QPB + qi;

        float x = g_attn[m*32 + h*4 + p];
        float mx = x;
        mx = fmaxf(mx, __shfl_xor_sync(0xffffffffu, mx, 1));
        mx = fmaxf(mx, __shfl_xor_sync(0xffffffffu, mx, 2));
        float e = expf(x - mx);
        float se = e;
        se += __shfl_xor_sync(0xffffffffu, se, 1);
        se += __shfl_xor_sync(0xffffffffu, se, 2);
        g_attw[q] = e / se;

        float rx = rp[m*3], ry = rp[m*3+1], rz = rp[m*3+2];
        const float* of = g_off + m*96 + h*12 + p*3;
        float sx = rx + of[0], sy = ry + of[1], sz = rz + of[2];
        g_sl[q] = make_float4(sx, sy, sz, sx*sx + sy*sy + sz*sz);
        int key = morton(sx, sy, sz);
        skey[qi] = key;
        atomicAdd(&cnt[key], 1);
    }
    __syncthreads();

    int s = cnt[tid], v = s;
    #pragma unroll
    for (int off = 1; off < 32; off <<= 1) {
        int u = __shfl_up_sync(0xffffffffu, v, off);
        if (lane >= off) v += u;
    }
    if (lane == 31) wsum[w] = v;
    __syncthreads();
    if (tid == 0) {
        int acc = 0;
        #pragma unroll
        for (int i = 0; i < 16; i++) { int t = wsum[i]; wsum[i] = acc; acc += t; }
    }
    __syncthreads();
    bstart[tid] = v - s + wsum[w];
    __syncthreads();
    #pragma unroll
    for (int j = 0; j < 8; j++) {
        int qi = tid + j*512;
        int slot = atomicAdd(&bstart[skey[qi]], 1);
        g_qperm[b*QPB + slot] = qi;
    }
}

// ---------------- seeded top-4 NN, warp-uniform branch ----------------------
#define INS(dd, ii) { \
    bool c3 = (dd) < d3, c2 = (dd) < d2, c1 = (dd) < d1, c0 = (dd) < d0; \
    d3 = c3 ? (c2 ? d2 : (dd)) : d3;  i3 = c3 ? (c2 ? i2 : (ii)) : i3; \
    d2 = c2 ? (c1 ? d1 : (dd)) : d2;  i2 = c2 ? (c1 ? i1 : (ii)) : i2; \
    d1 = c1 ? (c0 ? d0 : (dd)) : d1;  i1 = c1 ? (c0 ? i0 : (ii)) : i1; \
    d0 = c0 ? (dd) : d0;              i0 = c0 ? (ii) : i0; }

#define INSV(vv) { \
    bool c3 = (vv) < e3, c2 = (vv) < e2, c1 = (vv) < e1, c0 = (vv) < e0; \
    e3 = c3 ? (c2 ? e2 : (vv)) : e3; \
    e2 = c2 ? (c1 ? e1 : (vv)) : e2; \
    e1 = c1 ? (c0 ? e0 : (vv)) : e1; \
    e0 = c0 ? (vv) : e0; }

__global__ void knn_k() {
    // pre-packed f32x2 pairs: sA[j]=(x01,y01), sB[j]=(z01,w01)
    __shared__ ulonglong2 sA[LB/2];
    __shared__ ulonglong2 sB[LB/2];
    __shared__ int        sIdx[LB];
    __shared__ float4     sBnd[NTILE];
    const int b = blockIdx.y;                         // 0..15 (= n*8+h)
    const int n = b & (NB - 1);                       // ref set = rp[b % N]
    const int tid = threadIdx.x;

    for (int j = tid; j < LB/2; j += 256) {
        float4 r0 = g_refPts[n][2*j];
        float4 r1 = g_refPts[n][2*j + 1];
        sA[j] = make_ulonglong2(pk(r0.x, r1.x), pk(r0.y, r1.y));
        sB[j] = make_ulonglong2(pk(r0.z, r1.z), pk(r0.w, r1.w));
        sIdx[2*j]     = g_refIdx[n][2*j];
        sIdx[2*j + 1] = g_refIdx[n][2*j + 1];
    }
    if (tid < NTILE) sBnd[tid] = g_tileBnd[n][tid];
    __syncthreads();

    const int pos = blockIdx.x*256 + tid;             // Morton-sorted position
    const int qi = g_qperm[b*QPB + pos];
    const int q = b*QPB + qi;
    float4 s = g_sl[q];

    const u64 sx2 = pk(s.x, s.x), sy2 = pk(s.y, s.y), sz2 = pk(s.z, s.z), sw2 = pk(s.w, s.w);
    const u64 m2 = pk(-2.f, -2.f);

    // --- nearest tile center (branch-free) ---
    float best = 3.4e38f; int bt = 0;
    #pragma unroll
    for (int t = 0; t < NTILE; t++) {
        float4 bd = sBnd[t];
        float dx = s.x - bd.x, dy = s.y - bd.y, dz = s.z - bd.z;
        float dc = dx*dx + dy*dy + dz*dz;
        bool c = dc < best;
        best = c ? dc : best;
        bt = c ? t : bt;
    }

    // --- seed: 4th-smallest distance in home tile (values only) ---
    float e0 = 3.4e38f, e1 = 3.4e38f, e2 = 3.4e38f, e3 = 3.4e38f;
    {
        const int jb = bt*(TS/2);
        #pragma unroll
        for (int j = 0; j < TS/2; j++) {
            ulonglong2 a  = sA[jb + j];
            ulonglong2 bb = sB[jb + j];
            u64 dot = mul2(a.x, sx2);
            dot = fma2(a.y, sy2, dot);
            dot = fma2(bb.x, sz2, dot);
            u64 dd2 = fma2(dot, m2, add2(bb.y, sw2));
            float lo, hi; upk(dd2, lo, hi);
            INSV(lo);
            INSV(hi);
        }
    }
    const float dinit = e3 * 1.0001f + 1e-7f;   // strict upper bound on final d3

    float d0 = dinit, d1 = dinit, d2 = dinit, d3 = dinit;
    int   i0 = 0, i1 = 0, i2 = 0, i3 = 0;

    // --- full sweep; ladder behind an unpredicable warp-uniform branch ---
    #pragma unroll 4
    for (int j = 0; j < LB/2; j++) {
        ulonglong2 a  = sA[j];
        ulonglong2 bb = sB[j];
        u64 dot = mul2(a.x, sx2);
        dot = fma2(a.y, sy2, dot);
        dot = fma2(bb.x, sz2, dot);
        u64 dd2 = fma2(dot, m2, add2(bb.y, sw2));
        float lo, hi; upk(dd2, lo, hi);
        if (__ballot_sync(0xffffffffu, fminf(lo, hi) < d3)) {
            INS(lo, 2*j);
            INS(hi, 2*j + 1);
        }
    }

    float t0 = sqrtf(fmaxf(d0, 1e-12f));
    float t1 = sqrtf(fmaxf(d1, 1e-12f));
    float t2 = sqrtf(fmaxf(d2, 1e-12f));
    float t3 = sqrtf(fmaxf(d3, 1e-12f));
    float w0 = 1.f/(t0 + 1e-8f), w1 = 1.f/(t1 + 1e-8f);
    float w2 = 1.f/(t2 + 1e-8f), w3 = 1.f/(t3 + 1e-8f);
    float scale = g_attw[q] / (w0 + w1 + w2 + w3);

    *(int4*)  (g_idx + 4*q) = make_int4(sIdx[i0], sIdx[i1], sIdx[i2], sIdx[i3]);
    *(float4*)(g_w   + 4*q) = make_float4(w0*scale, w1*scale, w2*scale, w3*scale);
}

// ---------------- gather values + weighted sum (float4 channels) -----------
__global__ void combine_k() {
    int t = blockIdx.x*256 + threadIdx.x;   // 0..131071
    int g = t >> 3;                          // (b,l): 0..16383
    int c4 = (t & 7) << 2;                   // channel offset 0,4,..28
    int b = g >> 10, l = g & (LB - 1);
    int n_q = b >> 3, h_q = b & 7;           // output placement
    int n_v = b & 1,  h_v = b >> 1;          // value slice (reference quirk)
    const float* vb = g_val + n_v*(LB*EB) + h_v*DB + c4;
    int qb = (b*QPB + l*PB)*KK;
    const int4*   ip = (const int4*)  (g_idx + qb);
    const float4* wp = (const float4*)(g_w   + qb);
    float4 acc = make_float4(0.f, 0.f, 0.f, 0.f);
    #pragma unroll
    for (int j = 0; j < 4; j++) {
        int4   ii = ip[j];
        float4 ww = wp[j];
        float4 v;
        v = *(const float4*)(vb + ii.x*EB);
        acc.x = fmaf(ww.x, v.x, acc.x); acc.y = fmaf(ww.x, v.y, acc.y);
        acc.z = fmaf(ww.x, v.z, acc.z); acc.w = fmaf(ww.x, v.w, acc.w);
        v = *(const float4*)(vb + ii.y*EB);
        acc.x = fmaf(ww.y, v.x, acc.x); acc.y = fmaf(ww.y, v.y, acc.y);
        acc.z = fmaf(ww.y, v.z, acc.z); acc.w = fmaf(ww.y, v.w, acc.w);
        v = *(const float4*)(vb + ii.z*EB);
        acc.x = fmaf(ww.z, v.x, acc.x); acc.y = fmaf(ww.z, v.y, acc.y);
        acc.z = fmaf(ww.z, v.z, acc.z); acc.w = fmaf(ww.z, v.w, acc.w);
        v = *(const float4*)(vb + ii.w*EB);
        acc.x = fmaf(ww.w, v.x, acc.x); acc.y = fmaf(ww.w, v.y, acc.y);
        acc.z = fmaf(ww.w, v.z, acc.z); acc.w = fmaf(ww.w, v.w, acc.w);
    }
    *(float4*)(g_A + (n_q*LB + l)*EB + h_q*DB + c4) = acc;
}

// ---------------------------------------------------------------------------
extern "C" void kernel_launch(void* const* d_in, const int* in_sizes, int n_in,
                              void* d_out, int out_size) {
    const float* q      = (const float*)d_in[0];
    const float* rp     = (const float*)d_in[1];
    const float* W_off  = (const float*)d_in[2];
    const float* b_off  = (const float*)d_in[3];
    const float* W_attn = (const float*)d_in[4];
    const float* b_attn = (const float*)d_in[5];
    const float* W_val  = (const float*)d_in[6];
    const float* b_val  = (const float*)d_in[7];
    const float* W_out  = (const float*)d_in[8];
    const float* b_out  = (const float*)d_in[9];
    float* out = (float*)d_out;

    dim3 blk(256);
    refsort_k <<<2, blk>>>(rp);
    gemm_oa_k <<<dim3(2, 32), blk>>>(q, W_off, b_off, W_attn, b_attn);
    sortprep_k<<<16, 512>>>(rp);
    gemm_val_k<<<dim3(4, 32), blk>>>(q, W_val, b_val);
    knn_k     <<<dim3(16, 16), blk>>>();
    combine_k <<<512, blk>>>();
    gemm_out_k<<<dim3(4, 32), blk>>>(W_out, b_out, out);
}

// round 8
// speedup vs baseline: 1.1447x; 1.1447x over previous
#include <cuda_runtime.h>

// Problem constants
#define NB 2
#define LB 1024
#define EB 256
#define HB 8
#define PB 4
#define KK 4
#define DB 32
#define MROWS (NB*LB)        // 2048
#define NH (NB*HB)           // 16
#define QPB (LB*PB)          // 4096 queries per batch-head
#define QTOT (NH*QPB)        // 65536
#define NTILE 64             // ref tiles per batch
#define TS 16                // refs per tile

// ---------------- scratch (device globals) ---------------------------------
__device__ float  g_val [MROWS*EB];
__device__ float  g_off [MROWS*96];
__device__ float  g_attn[MROWS*32];
__device__ float  g_attw[QTOT];
__device__ float4 g_sl  [QTOT];             // sampling loc (x,y,z,|s|^2)
__device__ int    g_qperm[QTOT];            // per-b permutation (Morton sorted)
__device__ float4 g_refPts[NB][LB];         // Morton-sorted refs (x,y,z,|r|^2)
__device__ int    g_refIdx[NB][LB];         // original ref index
__device__ float4 g_tileBnd[NB][NTILE];     // tile center (xyz) + radius (w)
__device__ int    g_idx [QTOT*KK];
__device__ float  g_w   [QTOT*KK];
__device__ float  g_A   [MROWS*EB];

// ---------------- packed f32x2 helpers (Blackwell) --------------------------
typedef unsigned long long u64;
__device__ __forceinline__ u64 pk(float lo, float hi) {
    u64 v; asm("mov.b64 %0, {%1, %2};" : "=l"(v) : "f"(lo), "f"(hi)); return v;
}
__device__ __forceinline__ void upk(u64 v, float& lo, float& hi) {
    asm("mov.b64 {%0, %1}, %2;" : "=f"(lo), "=f"(hi) : "l"(v));
}
__device__ __forceinline__ u64 fma2(u64 a, u64 b, u64 c) {
    u64 d; asm("fma.rn.f32x2 %0, %1, %2, %3;" : "=l"(d) : "l"(a), "l"(b), "l"(c)); return d;
}
__device__ __forceinline__ u64 mul2(u64 a, u64 b) {
    u64 d; asm("mul.rn.f32x2 %0, %1, %2;" : "=l"(d) : "l"(a), "l"(b)); return d;
}
__device__ __forceinline__ u64 add2(u64 a, u64 b) {
    u64 d; asm("add.rn.f32x2 %0, %1, %2;" : "=l"(d) : "l"(a), "l"(b)); return d;
}

// ============================================================================
// Double-buffered 64x64 SGEMM kernels (single sync per 16-k chunk)
// ============================================================================

// ---- merged projection: C[2048, 384v] = q @ [W_val | W_off | W_attn] ------
__device__ __forceinline__ float loadBproj(const float* __restrict__ Wv,
                                           const float* __restrict__ Wo,
                                           const float* __restrict__ Wa,
                                           int gk, int gn) {
    if (gn < 256)      return Wv[gk*256 + gn];
    else if (gn < 352) return Wo[gk*96  + (gn - 256)];
    else               return Wa[gk*32  + (gn - 352)];
}

__global__ void proj_gemm_k(const float* __restrict__ A,
                            const float* __restrict__ Wv, const float* __restrict__ bv,
                            const float* __restrict__ Wo, const float* __restrict__ bo,
                            const float* __restrict__ Wa, const float* __restrict__ ba) {
    __shared__ float As[2][16][64];
    __shared__ float Bs[2][16][68];
    const int tid = threadIdx.x;
    const int tx = tid & 15, ty = tid >> 4;
    const int rowBase = blockIdx.y * 64;
    const int colBase = blockIdx.x * 64;
    float acc[4][4];
    #pragma unroll
    for (int i = 0; i < 4; i++)
        #pragma unroll
        for (int j = 0; j < 4; j++) acc[i][j] = 0.f;

    // prologue: chunk 0 -> buffer 0
    #pragma unroll
    for (int i = 0; i < 4; i++) {
        int idx = tid + i*256;
        int m = idx >> 4, k = idx & 15;
        As[0][k][m] = A[(rowBase + m)*256 + k];
        int k2 = idx >> 6, n = idx & 63;
        Bs[0][k2][n] = loadBproj(Wv, Wo, Wa, k2, colBase + n);
    }
    __syncthreads();

    #pragma unroll 4
    for (int k0 = 0; k0 < 256; k0 += 16) {
        const int cur = (k0 >> 4) & 1, nxt = cur ^ 1;
        float ra[4], rb[4];
        const bool more = (k0 + 16) < 256;
        if (more) {
            #pragma unroll
            for (int i = 0; i < 4; i++) {
                int idx = tid + i*256;
                int m = idx >> 4, k = idx & 15;
                ra[i] = A[(rowBase + m)*256 + k0 + 16 + k];
                int k2 = idx >> 6, n = idx & 63;
                rb[i] = loadBproj(Wv, Wo, Wa, k0 + 16 + k2, colBase + n);
            }
        }
        #pragma unroll
        for (int kk = 0; kk < 16; kk++) {
            float4 av = *(const float4*)&As[cur][kk][ty*4];
            float4 bvv = *(const float4*)&Bs[cur][kk][tx*4];
            float a[4] = {av.x, av.y, av.z, av.w};
            float b[4] = {bvv.x, bvv.y, bvv.z, bvv.w};
            #pragma unroll
            for (int i = 0; i < 4; i++)
                #pragma unroll
                for (int j = 0; j < 4; j++)
                    acc[i][j] = fmaf(a[i], b[j], acc[i][j]);
        }
        if (more) {
            #pragma unroll
            for (int i = 0; i < 4; i++) {
                int idx = tid + i*256;
                int m = idx >> 4, k = idx & 15;
                As[nxt][k][m] = ra[i];
                int k2 = idx >> 6, n = idx & 63;
                Bs[nxt][k2][n] = rb[i];
            }
            __syncthreads();
        }
    }

    #pragma unroll
    for (int i = 0; i < 4; i++) {
        int gm = rowBase + ty*4 + i;
        #pragma unroll
        for (int j = 0; j < 4; j++) {
            int gn = colBase + tx*4 + j;
            float v = acc[i][j];
            if (gn < 256)      g_val[gm*256 + gn]          = v + bv[gn];
            else if (gn < 352) g_off[gm*96  + (gn - 256)]  = v + bo[gn - 256];
            else               g_attn[gm*32 + (gn - 352)]  = v + ba[gn - 352];
        }
    }
}

// ---- output GEMM: out[2048,256] = g_A @ W_out + b_out ----------------------
__global__ void out_gemm_k(const float* __restrict__ B,
                           const float* __restrict__ bias,
                           float* __restrict__ C) {
    __shared__ float As[2][16][64];
    __shared__ float Bs[2][16][68];
    const float* A = g_A;
    const int tid = threadIdx.x;
    const int tx = tid & 15, ty = tid >> 4;
    const int rowBase = blockIdx.y * 64;
    const int colBase = blockIdx.x * 64;
    float acc[4][4];
    #pragma unroll
    for (int i = 0; i < 4; i++)
        #pragma unroll
        for (int j = 0; j < 4; j++) acc[i][j] = 0.f;

    #pragma unroll
    for (int i = 0; i < 4; i++) {
        int idx = tid + i*256;
        int m = idx >> 4, k = idx & 15;
        As[0][k][m] = A[(rowBase + m)*256 + k];
        int k2 = idx >> 6, n = idx & 63;
        Bs[0][k2][n] = B[k2*256 + colBase + n];
    }
    __syncthreads();

    #pragma unroll 4
    for (int k0 = 0; k0 < 256; k0 += 16) {
        const int cur = (k0 >> 4) & 1, nxt = cur ^ 1;
        float ra[4], rb[4];
        const bool more = (k0 + 16) < 256;
        if (more) {
            #pragma unroll
            for (int i = 0; i < 4; i++) {
                int idx = tid + i*256;
                int m = idx >> 4, k = idx & 15;
                ra[i] = A[(rowBase + m)*256 + k0 + 16 + k];
                int k2 = idx >> 6, n = idx & 63;
                rb[i] = B[(k0 + 16 + k2)*256 + colBase + n];
            }
        }
        #pragma unroll
        for (int kk = 0; kk < 16; kk++) {
            float4 av = *(const float4*)&As[cur][kk][ty*4];
            float4 bvv = *(const float4*)&Bs[cur][kk][tx*4];
            float a[4] = {av.x, av.y, av.z, av.w};
            float b[4] = {bvv.x, bvv.y, bvv.z, bvv.w};
            #pragma unroll
            for (int i = 0; i < 4; i++)
                #pragma unroll
                for (int j = 0; j < 4; j++)
                    acc[i][j] = fmaf(a[i], b[j], acc[i][j]);
        }
        if (more) {
            #pragma unroll
            for (int i = 0; i < 4; i++) {
                int idx = tid + i*256;
                int m = idx >> 4, k = idx & 15;
                As[nxt][k][m] = ra[i];
                int k2 = idx >> 6, n = idx & 63;
                Bs[nxt][k2][n] = rb[i];
            }
            __syncthreads();
        }
    }

    #pragma unroll
    for (int i = 0; i < 4; i++) {
        int gm = rowBase + ty*4 + i;
        #pragma unroll
        for (int j = 0; j < 4; j++) {
            int gn = colBase + tx*4 + j;
            C[gm*256 + gn] = acc[i][j] + bias[gn];
        }
    }
}

// ---------------- Morton helpers -------------------------------------------
__device__ __forceinline__ int spread3(int x) {
    return (x & 1) | ((x & 2) << 2) | ((x & 4) << 4);
}
__device__ __forceinline__ int cell8(float v) {
    int c = (int)floorf(v * 8.f);
    return min(max(c, 0), 7);
}
__device__ __forceinline__ int morton(float x, float y, float z) {
    return spread3(cell8(x)) | (spread3(cell8(y)) << 1) | (spread3(cell8(z)) << 2);
}

// ---------------- ref Morton sort + tile bounds (grid=2, block=256) --------
__global__ void refsort_k(const float* __restrict__ rp) {
    __shared__ float sx[LB], sy[LB], sz[LB];
    __shared__ int   sidx[LB], skey[LB];
    __shared__ int   cnt[512], bstart[512];
    __shared__ int   wsum[8];
    const int n = blockIdx.x, tid = threadIdx.x;
    const int lane = tid & 31, w = tid >> 5;
    const float* rpb = rp + n*LB*3;

    cnt[tid] = 0; cnt[tid + 256] = 0;
    __syncthreads();
    #pragma unroll
    for (int j = 0; j < 4; j++) {
        int i = tid + j*256;
        float x = rpb[3*i], y = rpb[3*i+1], z = rpb[3*i+2];
        int key = morton(x, y, z);
        skey[i] = key;
        atomicAdd(&cnt[key], 1);
    }
    __syncthreads();
    int c0 = cnt[2*tid], c1 = cnt[2*tid + 1];
    int s = c0 + c1, v = s;
    #pragma unroll
    for (int off = 1; off < 32; off <<= 1) {
        int u = __shfl_up_sync(0xffffffffu, v, off);
        if (lane >= off) v += u;
    }
    if (lane == 31) wsum[w] = v;
    __syncthreads();
    if (tid == 0) {
        int acc = 0;
        #pragma unroll
        for (int i = 0; i < 8; i++) { int t = wsum[i]; wsum[i] = acc; acc += t; }
    }
    __syncthreads();
    int excl = v - s + wsum[w];
    bstart[2*tid] = excl; bstart[2*tid + 1] = excl + c0;
    __syncthreads();
    #pragma unroll
    for (int j = 0; j < 4; j++) {
        int i = tid + j*256;
        int slot = atomicAdd(&bstart[skey[i]], 1);
        sx[slot] = rpb[3*i]; sy[slot] = rpb[3*i+1]; sz[slot] = rpb[3*i+2];
        sidx[slot] = i;
    }
    __syncthreads();
    #pragma unroll
    for (int j = 0; j < 4; j++) {
        int i = tid + j*256;
        float x = sx[i], y = sy[i], z = sz[i];
        g_refPts[n][i] = make_float4(x, y, z, x*x + y*y + z*z);
        g_refIdx[n][i] = sidx[i];
    }
    if (tid < NTILE) {
        float mnx = 3e38f, mny = 3e38f, mnz = 3e38f;
        float mxx = -3e38f, mxy = -3e38f, mxz = -3e38f;
        #pragma unroll
        for (int p = 0; p < TS; p++) {
            int i = tid*TS + p;
            mnx = fminf(mnx, sx[i]); mxx = fmaxf(mxx, sx[i]);
            mny = fminf(mny, sy[i]); mxy = fmaxf(mxy, sy[i]);
            mnz = fminf(mnz, sz[i]); mxz = fmaxf(mxz, sz[i]);
        }
        float cx = 0.5f*(mnx + mxx), cy = 0.5f*(mny + mxy), cz = 0.5f*(mnz + mxz);
        float ex = 0.5f*(mxx - mnx), ey = 0.5f*(mxy - mny), ez = 0.5f*(mxz - mnz);
        float rad = sqrtf(ex*ex + ey*ey + ez*ez) + 1e-3f;
        g_tileBnd[n][tid] = make_float4(cx, cy, cz, rad);
    }
}

// ---------------- fused prep + Morton counting sort (16 blocks, 512 thr) ---
__global__ void sortprep_k(const float* __restrict__ rp) {
    __shared__ int skey[QPB];
    __shared__ int cnt[512];
    __shared__ int bstart[512];
    __shared__ int wsum[16];
    const int b = blockIdx.x, tid = threadIdx.x;
    const int lane = tid & 31, w = tid >> 5;
    const int n = b >> 3, h = b & 7;

    cnt[tid] = 0;
    __syncthreads();

    #pragma unroll
    for (int j = 0; j < 8; j++) {
        int qi = tid + j*512;
        int l = qi >> 2, p = qi & 3;
        int m = n*LB + l;
        int q = b*QPB + qi;

        float x = g_attn[m*32 + h*4 + p];
        float mx = x;
        mx = fmaxf(mx, __shfl_xor_sync(0xffffffffu, mx, 1));
        mx = fmaxf(mx, __shfl_xor_sync(0xffffffffu, mx, 2));
        float e = expf(x - mx);
        float se = e;
        se += __shfl_xor_sync(0xffffffffu, se, 1);
        se += __shfl_xor_sync(0xffffffffu, se, 2);
        g_attw[q] = e / se;

        float rx = rp[m*3], ry = rp[m*3+1], rz = rp[m*3+2];
        const float* of = g_off + m*96 + h*12 + p*3;
        float sx = rx + of[0], sy = ry + of[1], sz = rz + of[2];
        g_sl[q] = make_float4(sx, sy, sz, sx*sx + sy*sy + sz*sz);
        int key = morton(sx, sy, sz);
        skey[qi] = key;
        atomicAdd(&cnt[key], 1);
    }
    __syncthreads();

    int s = cnt[tid], v = s;
    #pragma unroll
    for (int off = 1; off < 32; off <<= 1) {
        int u = __shfl_up_sync(0xffffffffu, v, off);
        if (lane >= off) v += u;
    }
    if (lane == 31) wsum[w] = v;
    __syncthreads();
    if (tid == 0) {
        int acc = 0;
        #pragma unroll
        for (int i = 0; i < 16; i++) { int t = wsum[i]; wsum[i] = acc; acc += t; }
    }
    __syncthreads();
    bstart[tid] = v - s + wsum[w];
    __syncthreads();
    #pragma unroll
    for (int j = 0; j < 8; j++) {
        int qi = tid + j*512;
        int slot = atomicAdd(&bstart[skey[qi]], 1);
        g_qperm[b*QPB + slot] = qi;
    }
}

// ---------------- seeded top-4 NN, warp-uniform branch ----------------------
#define INS(dd, ii) { \
    bool c3 = (dd) < d3, c2 = (dd) < d2, c1 = (dd) < d1, c0 = (dd) < d0; \
    d3 = c3 ? (c2 ? d2 : (dd)) : d3;  i3 = c3 ? (c2 ? i2 : (ii)) : i3; \
    d2 = c2 ? (c1 ? d1 : (dd)) : d2;  i2 = c2 ? (c1 ? i1 : (ii)) : i2; \
    d1 = c1 ? (c0 ? d0 : (dd)) : d1;  i1 = c1 ? (c0 ? i0 : (ii)) : i1; \
    d0 = c0 ? (dd) : d0;              i0 = c0 ? (ii) : i0; }

#define INSV(vv) { \
    bool c3 = (vv) < e3, c2 = (vv) < e2, c1 = (vv) < e1, c0 = (vv) < e0; \
    e3 = c3 ? (c2 ? e2 : (vv)) : e3; \
    e2 = c2 ? (c1 ? e1 : (vv)) : e2; \
    e1 = c1 ? (c0 ? e0 : (vv)) : e1; \
    e0 = c0 ? (vv) : e0; }

__global__ void knn_k() {
    __shared__ ulonglong2 sA[LB/2];
    __shared__ ulonglong2 sB[LB/2];
    __shared__ int        sIdx[LB];
    __shared__ float4     sBnd[NTILE];
    const int b = blockIdx.y;
    const int n = b & (NB - 1);
    const int tid = threadIdx.x;

    for (int j = tid; j < LB/2; j += 256) {
        float4 r0 = g_refPts[n][2*j];
        float4 r1 = g_refPts[n][2*j + 1];
        sA[j] = make_ulonglong2(pk(r0.x, r1.x), pk(r0.y, r1.y));
        sB[j] = make_ulonglong2(pk(r0.z, r1.z), pk(r0.w, r1.w));
        sIdx[2*j]     = g_refIdx[n][2*j];
        sIdx[2*j + 1] = g_refIdx[n][2*j + 1];
    }
    if (tid < NTILE) sBnd[tid] = g_tileBnd[n][tid];
    __syncthreads();

    const int pos = blockIdx.x*256 + tid;
    const int qi = g_qperm[b*QPB + pos];
    const int q = b*QPB + qi;
    float4 s = g_sl[q];

    const u64 sx2 = pk(s.x, s.x), sy2 = pk(s.y, s.y), sz2 = pk(s.z, s.z), sw2 = pk(s.w, s.w);
    const u64 m2 = pk(-2.f, -2.f);

    float best = 3.4e38f; int bt = 0;
    #pragma unroll
    for (int t = 0; t < NTILE; t++) {
        float4 bd = sBnd[t];
        float dx = s.x - bd.x, dy = s.y - bd.y, dz = s.z - bd.z;
        float dc = dx*dx + dy*dy + dz*dz;
        bool c = dc < best;
        best = c ? dc : best;
        bt = c ? t : bt;
    }

    float e0 = 3.4e38f, e1 = 3.4e38f, e2 = 3.4e38f, e3 = 3.4e38f;
    {
        const int jb = bt*(TS/2);
        #pragma unroll
        for (int j = 0; j < TS/2; j++) {
            ulonglong2 a  = sA[jb + j];
            ulonglong2 bb = sB[jb + j];
            u64 dot = mul2(a.x, sx2);
            dot = fma2(a.y, sy2, dot);
            dot = fma2(bb.x, sz2, dot);
            u64 dd2 = fma2(dot, m2, add2(bb.y, sw2));
            float lo, hi; upk(dd2, lo, hi);
            INSV(lo);
            INSV(hi);
        }
    }
    const float dinit = e3 * 1.0001f + 1e-7f;

    float d0 = dinit, d1 = dinit, d2 = dinit, d3 = dinit;
    int   i0 = 0, i1 = 0, i2 = 0, i3 = 0;

    #pragma unroll 4
    for (int j = 0; j < LB/2; j++) {
        ulonglong2 a  = sA[j];
        ulonglong2 bb = sB[j];
        u64 dot = mul2(a.x, sx2);
        dot = fma2(a.y, sy2, dot);
        dot = fma2(bb.x, sz2, dot);
        u64 dd2 = fma2(dot, m2, add2(bb.y, sw2));
        float lo, hi; upk(dd2, lo, hi);
        if (__ballot_sync(0xffffffffu, fminf(lo, hi) < d3)) {
            INS(lo, 2*j);
            INS(hi, 2*j + 1);
        }
    }

    float t0 = sqrtf(fmaxf(d0, 1e-12f));
    float t1 = sqrtf(fmaxf(d1, 1e-12f));
    float t2 = sqrtf(fmaxf(d2, 1e-12f));
    float t3 = sqrtf(fmaxf(d3, 1e-12f));
    float w0 = 1.f/(t0 + 1e-8f), w1 = 1.f/(t1 + 1e-8f);
    float w2 = 1.f/(t2 + 1e-8f), w3 = 1.f/(t3 + 1e-8f);
    float scale = g_attw[q] / (w0 + w1 + w2 + w3);

    *(int4*)  (g_idx + 4*q) = make_int4(sIdx[i0], sIdx[i1], sIdx[i2], sIdx[i3]);
    *(float4*)(g_w   + 4*q) = make_float4(w0*scale, w1*scale, w2*scale, w3*scale);
}

// ---------------- gather values + weighted sum (float4 channels) -----------
__global__ void combine_k() {
    int t = blockIdx.x*256 + threadIdx.x;
    int g = t >> 3;
    int c4 = (t & 7) << 2;
    int b = g >> 10, l = g & (LB - 1);
    int n_q = b >> 3, h_q = b & 7;
    int n_v = b & 1,  h_v = b >> 1;
    const float* vb = g_val + n_v*(LB*EB) + h_v*DB + c4;
    int qb = (b*QPB + l*PB)*KK;
    const int4*   ip = (const int4*)  (g_idx + qb);
    const float4* wp = (const float4*)(g_w   + qb);
    float4 acc = make_float4(0.f, 0.f, 0.f, 0.f);
    #pragma unroll
    for (int j = 0; j < 4; j++) {
        int4   ii = ip[j];
        float4 ww = wp[j];
        float4 v;
        v = *(const float4*)(vb + ii.x*EB);
        acc.x = fmaf(ww.x, v.x, acc.x); acc.y = fmaf(ww.x, v.y, acc.y);
        acc.z = fmaf(ww.x, v.z, acc.z); acc.w = fmaf(ww.x, v.w, acc.w);
        v = *(const float4*)(vb + ii.y*EB);
        acc.x = fmaf(ww.y, v.x, acc.x); acc.y = fmaf(ww.y, v.y, acc.y);
        acc.z = fmaf(ww.y, v.z, acc.z); acc.w = fmaf(ww.y, v.w, acc.w);
        v = *(const float4*)(vb + ii.z*EB);
        acc.x = fmaf(ww.z, v.x, acc.x); acc.y = fmaf(ww.z, v.y, acc.y);
        acc.z = fmaf(ww.z, v.z, acc.z); acc.w = fmaf(ww.z, v.w, acc.w);
        v = *(const float4*)(vb + ii.w*EB);
        acc.x = fmaf(ww.w, v.x, acc.x); acc.y = fmaf(ww.w, v.y, acc.y);
        acc.z = fmaf(ww.w, v.z, acc.z); acc.w = fmaf(ww.w, v.w, acc.w);
    }
    *(float4*)(g_A + (n_q*LB + l)*EB + h_q*DB + c4) = acc;
}

// ---------------------------------------------------------------------------
extern "C" void kernel_launch(void* const* d_in, const int* in_sizes, int n_in,
                              void* d_out, int out_size) {
    const float* q      = (const float*)d_in[0];
    const float* rp     = (const float*)d_in[1];
    const float* W_off  = (const float*)d_in[2];
    const float* b_off  = (const float*)d_in[3];
    const float* W_attn = (const float*)d_in[4];
    const float* b_attn = (const float*)d_in[5];
    const float* W_val  = (const float*)d_in[6];
    const float* b_val  = (const float*)d_in[7];
    const float* W_out  = (const float*)d_in[8];
    const float* b_out  = (const float*)d_in[9];
    float* out = (float*)d_out;

    dim3 blk(256);
    refsort_k <<<2, blk>>>(rp);
    proj_gemm_k<<<dim3(6, 32), blk>>>(q, W_val, b_val, W_off, b_off, W_attn, b_attn);
    sortprep_k<<<16, 512>>>(rp);
    knn_k     <<<dim3(16, 16), blk>>>();
    combine_k <<<512, blk>>>();
    out_gemm_k<<<dim3(4, 32), blk>>>(W_out, b_out, out);
}